// round 8
// baseline (speedup 1.0000x reference)
#include <cuda_runtime.h>
#include <cuda_bf16.h>
#include <cuda_fp16.h>
#include <cstdint>

#define N_OPT 16
#define OUT_F 1024
#define IN_F  1024
#define BATCH 8
#define A_DIM 512

// GEMM tiling
#define BM 128
#define BN 256
#define BKC 64                    // fp16 K elems per stage (one 128B row per M/N row)
#define NSTAGE 4
#define NKC (IN_F / BKC)          // 16
#define MT (A_DIM / BM)           // 4
#define NTG (OUT_F / BN)          // 4

#define A_BLK_BYTES (BM * 128)    // 16384
#define B_BLK_BYTES (BN * 128)    // 32768
#define STAGE_BYTES (A_BLK_BYTES + B_BLK_BYTES)   // 49152
#define SMEM_BYTES  (1024 + NSTAGE * STAGE_BYTES) // 197632

// fused prep kernel block ranges
#define MIXW_BLOCKS 512           // (OUT_F*IN_F/8)/256
#define CONVX_BLOCKS 2048         // (BATCH*A_DIM*IN_F/8)/256
#define BIAS_BLOCKS 32            // BATCH*OUT_F/256
#define PREP_BLOCKS (MIXW_BLOCKS + CONVX_BLOCKS + BIAS_BLOCKS)

// ---- scratch (device globals; no allocation anywhere) ----
__device__ __align__(1024) __half g_xs[BATCH * A_DIM * IN_F];   // 8 MB staged fp16 x
__device__ __align__(1024) __half g_ws[BATCH * OUT_F * IN_F];   // 16 MB staged fp16 w_mixed
__device__ float g_bmix[BATCH * OUT_F];

// ================= PTX helpers (plain-sm_103-safe) =================
__device__ __forceinline__ uint32_t smem_u32(const void* p) {
    uint32_t a;
    asm("{ .reg .u64 t; cvta.to.shared.u64 t, %1; cvt.u32.u64 %0, t; }" : "=r"(a) : "l"(p));
    return a;
}
#define MBAR_INIT(addr, cnt) \
    asm volatile("mbarrier.init.shared.b64 [%0], %1;" :: "r"(addr), "r"(cnt) : "memory")
#define MBAR_EXPECT_TX(addr, bytes) \
    asm volatile("mbarrier.arrive.expect_tx.shared.b64 _, [%0], %1;" :: "r"(addr), "r"(bytes) : "memory")
#define MBAR_ARRIVE(addr) \
    asm volatile("mbarrier.arrive.shared.b64 _, [%0];" :: "r"(addr) : "memory")
__device__ __forceinline__ void mbar_wait(uint32_t mbar, uint32_t parity) {
    asm volatile(
        "{\n\t.reg .pred P;\n\t"
        "WL_%=:\n\t"
        "mbarrier.try_wait.parity.acquire.cta.shared::cta.b64 P, [%0], %1, 0x989680;\n\t"
        "@!P bra WL_%=;\n\t}"
        :: "r"(mbar), "r"(parity) : "memory");
}
#define BULK_G2S(dst, src, bytes, mbar) \
    asm volatile("cp.async.bulk.shared::cluster.global.mbarrier::complete_tx::bytes [%0], [%1], %2, [%3];" \
                 :: "r"(dst), "l"(src), "r"(bytes), "r"(mbar) : "memory")

__device__ __forceinline__ void ldsm_x4(uint32_t* r, uint32_t addr) {
    asm volatile("ldmatrix.sync.aligned.m8n8.x4.shared.b16 {%0,%1,%2,%3}, [%4];"
        : "=r"(r[0]), "=r"(r[1]), "=r"(r[2]), "=r"(r[3]) : "r"(addr));
}
__device__ __forceinline__ void mma_f16(float* d, const uint32_t* a, const uint32_t* b) {
    asm volatile(
        "mma.sync.aligned.m16n8k16.row.col.f32.f16.f16.f32 "
        "{%0,%1,%2,%3}, {%4,%5,%6,%7}, {%8,%9}, {%0,%1,%2,%3};"
        : "+f"(d[0]), "+f"(d[1]), "+f"(d[2]), "+f"(d[3])
        : "r"(a[0]), "r"(a[1]), "r"(a[2]), "r"(a[3]), "r"(b[0]), "r"(b[1]));
}

__device__ __forceinline__ uint32_t pk2h(float a, float b) {
    __half2 t = __floats2half2_rn(a, b);
    return *reinterpret_cast<uint32_t*>(&t);
}

// ============================================================
// Fused prep kernel: one launch does all preprocessing.
//   blocks [0, 512):         mix weights -> staged fp16 w_mixed
//   blocks [512, 2560):      convert x   -> staged fp16 x
//   blocks [2560, 2592):     bias mix
// Staged layout (both operands): blocks of (rows x 64 fp16), row r is
// 128 B = 8 chunks of 16 B; chunk ch stored at byte ((ch ^ (r&7)) * 16).
// ============================================================
__global__ void __launch_bounds__(256)
prep_kernel(const float* __restrict__ W, const float* __restrict__ x,
            const float* __restrict__ bias, const float* __restrict__ sp) {
    const int blk = blockIdx.x;

    if (blk < MIXW_BLOCKS) {
        // ---------- mix weights ----------
        __shared__ float s_sp[BATCH * N_OPT];
        if (threadIdx.x < BATCH * N_OPT) s_sp[threadIdx.x] = sp[threadIdx.x];
        __syncthreads();

        const int t = blk * 256 + threadIdx.x;     // 8-elem k-group in plane
        const int i  = t >> 7;                     // out feature
        const int k0 = (t & 127) * 8;
        const int nt = i >> 8, r = i & 255;
        const int kc = k0 >> 6;
        const int ch = (k0 & 63) >> 3;

        const int plane4 = (OUT_F * IN_F) / 4;
        const float4* W4 = reinterpret_cast<const float4*>(W);

        float acc[BATCH][8];
#pragma unroll
        for (int b = 0; b < BATCH; b++)
#pragma unroll
            for (int q = 0; q < 8; q++) acc[b][q] = 0.f;

#pragma unroll
        for (int n = 0; n < N_OPT; n++) {
            float4 w0 = W4[(size_t)n * plane4 + t * 2];
            float4 w1 = W4[(size_t)n * plane4 + t * 2 + 1];
#pragma unroll
            for (int b = 0; b < BATCH; b++) {
                float s = s_sp[b * N_OPT + n];
                acc[b][0] += s * w0.x; acc[b][1] += s * w0.y;
                acc[b][2] += s * w0.z; acc[b][3] += s * w0.w;
                acc[b][4] += s * w1.x; acc[b][5] += s * w1.y;
                acc[b][6] += s * w1.z; acc[b][7] += s * w1.w;
            }
        }

        const uint32_t off = (uint32_t)r * 128 + (uint32_t)((ch ^ (r & 7)) * 16);
        char* base = (char*)g_ws;
#pragma unroll
        for (int b = 0; b < BATCH; b++) {
            uint4 hi = make_uint4(pk2h(acc[b][0], acc[b][1]), pk2h(acc[b][2], acc[b][3]),
                                  pk2h(acc[b][4], acc[b][5]), pk2h(acc[b][6], acc[b][7]));
            size_t blkoff = ((size_t)(b * NTG + nt) * NKC + kc) * B_BLK_BYTES;
            *reinterpret_cast<uint4*>(base + blkoff + off) = hi;
        }
    } else if (blk < MIXW_BLOCKS + CONVX_BLOCKS) {
        // ---------- convert x ----------
        const int t = (blk - MIXW_BLOCKS) * 256 + threadIdx.x;  // 8-elem k-group
        const int per_b8 = (A_DIM * IN_F) / 8;                  // 65536
        const int b = t / per_b8;
        const int rem = t % per_b8;
        const int a  = rem >> 7;
        const int k0 = (rem & 127) * 8;
        const int mt = a >> 7, r = a & 127;
        const int kc = k0 >> 6;
        const int ch = (k0 & 63) >> 3;

        const float4* x4 = reinterpret_cast<const float4*>(x);
        float4 v0 = x4[t * 2], v1 = x4[t * 2 + 1];

        uint4 hi = make_uint4(pk2h(v0.x, v0.y), pk2h(v0.z, v0.w),
                              pk2h(v1.x, v1.y), pk2h(v1.z, v1.w));

        const uint32_t off = (uint32_t)r * 128 + (uint32_t)((ch ^ (r & 7)) * 16);
        size_t blkoff = ((size_t)(b * MT + mt) * NKC + kc) * A_BLK_BYTES;
        *reinterpret_cast<uint4*>((char*)g_xs + blkoff + off) = hi;
    } else {
        // ---------- bias mix ----------
        int tid = (blk - MIXW_BLOCKS - CONVX_BLOCKS) * 256 + threadIdx.x;
        if (tid < BATCH * OUT_F) {
            int b = tid / OUT_F, i = tid % OUT_F;
            float acc = 0.f;
#pragma unroll
            for (int n = 0; n < N_OPT; n++) acc += sp[b * N_OPT + n] * bias[n * OUT_F + i];
            g_bmix[tid] = acc;
        }
    }
}

// ============================================================
// fp16 HMMA GEMM: out = fp16(x) * fp16(w_mixed)^T + bias.
// CTA 128x256, 8 warps (2x4), warp 64x64. cp.async.bulk 4-stage pipe,
// 64 K per stage = 4 k16 sub-steps with fragment double-buffering.
// grid (4,4,8) = 128 CTAs, one wave.
// ============================================================
__global__ void __launch_bounds__(256, 1)
gemm_mma_kernel(float* __restrict__ out) {
    extern __shared__ char dsmem[];
    const uint32_t sbase = smem_u32(dsmem);
    const uint32_t data  = (sbase + 64 + 1023u) & ~1023u;
    uint32_t mb_full[NSTAGE], mb_empty[NSTAGE];
#pragma unroll
    for (int s = 0; s < NSTAGE; s++) { mb_full[s] = sbase + s * 8; mb_empty[s] = sbase + 32 + s * 8; }

    const int tid = threadIdx.x, lane = tid & 31, wid = tid >> 5;
    const int wm = wid >> 2, wn = wid & 3;
    const int nt = blockIdx.x, mt = blockIdx.y, b = blockIdx.z;

    const char* Ag = (const char*)g_xs + (size_t)((b * MT + mt) * NKC) * A_BLK_BYTES;
    const char* Bg = (const char*)g_ws + (size_t)((b * NTG + nt) * NKC) * B_BLK_BYTES;

    if (tid == 0) {
#pragma unroll
        for (int s = 0; s < NSTAGE; s++) { MBAR_INIT(mb_full[s], 1); MBAR_INIT(mb_empty[s], 8); }
    }
    __syncthreads();

    if (tid == 0) {
#pragma unroll
        for (int p = 0; p < NSTAGE - 1; p++) {
            MBAR_EXPECT_TX(mb_full[p], STAGE_BYTES);
            BULK_G2S(data + p * STAGE_BYTES,               Ag + (size_t)p * A_BLK_BYTES, A_BLK_BYTES, mb_full[p]);
            BULK_G2S(data + p * STAGE_BYTES + A_BLK_BYTES, Bg + (size_t)p * B_BLK_BYTES, B_BLK_BYTES, mb_full[p]);
        }
    }

    const int a_row0 = wm * 64 + (lane & 15);
    const int a_csel = lane >> 4;
    const int b_row0 = wn * 64 + (lane & 7) + ((lane >> 4) << 3);
    const int b_csel = (lane >> 3) & 1;

    float acc[4][8][4];
#pragma unroll
    for (int mi = 0; mi < 4; mi++)
#pragma unroll
        for (int nj = 0; nj < 8; nj++)
#pragma unroll
            for (int q = 0; q < 4; q++) acc[mi][nj][q] = 0.f;

    for (int kc = 0; kc < NKC; kc++) {
        const int s = kc & (NSTAGE - 1);

        if (tid == 0 && kc + NSTAGE - 1 < NKC) {
            const int q = kc + NSTAGE - 1;
            const int ps = q & (NSTAGE - 1);
            if (kc >= 1) mbar_wait(mb_empty[ps], ((kc - 1) >> 2) & 1);
            MBAR_EXPECT_TX(mb_full[ps], STAGE_BYTES);
            BULK_G2S(data + ps * STAGE_BYTES,               Ag + (size_t)q * A_BLK_BYTES, A_BLK_BYTES, mb_full[ps]);
            BULK_G2S(data + ps * STAGE_BYTES + A_BLK_BYTES, Bg + (size_t)q * B_BLK_BYTES, B_BLK_BYTES, mb_full[ps]);
        }

        mbar_wait(mb_full[s], (kc >> 2) & 1);

        const uint32_t Abase = data + s * STAGE_BYTES;
        const uint32_t Bbase = Abase + A_BLK_BYTES;

        // fragment double-buffering across the four k16 sub-steps
        uint32_t Af[2][4][4], Bf[2][4][4];

        // load u=0 into buffer 0
#pragma unroll
        for (int mi = 0; mi < 4; mi++) {
            int row = a_row0 + mi * 16;
            int ch = a_csel ^ (row & 7);
            ldsm_x4(Af[0][mi], Abase + row * 128 + ch * 16);
        }
#pragma unroll
        for (int ni = 0; ni < 4; ni++) {
            int row = b_row0 + ni * 16;
            int ch = b_csel ^ (row & 7);
            ldsm_x4(Bf[0][ni], Bbase + row * 128 + ch * 16);
        }

#pragma unroll
        for (int u = 0; u < 4; u++) {
            const int cb = u & 1, nb = cb ^ 1;
            if (u < 3) {
                // prefetch sub-step u+1 while MMAs of u issue below
#pragma unroll
                for (int mi = 0; mi < 4; mi++) {
                    int row = a_row0 + mi * 16;
                    int ch = ((u + 1) * 2 + a_csel) ^ (row & 7);
                    ldsm_x4(Af[nb][mi], Abase + row * 128 + ch * 16);
                }
#pragma unroll
                for (int ni = 0; ni < 4; ni++) {
                    int row = b_row0 + ni * 16;
                    int ch = ((u + 1) * 2 + b_csel) ^ (row & 7);
                    ldsm_x4(Bf[nb][ni], Bbase + row * 128 + ch * 16);
                }
            }
            if (u == 3 && lane == 0) MBAR_ARRIVE(mb_empty[s]);

#pragma unroll
            for (int mi = 0; mi < 4; mi++)
#pragma unroll
                for (int ni = 0; ni < 4; ni++)
#pragma unroll
                    for (int jj = 0; jj < 2; jj++)
                        mma_f16(acc[mi][ni * 2 + jj], Af[cb][mi], &Bf[cb][ni][jj * 2]);
        }
    }

    // epilogue: add mixed bias, store
    const int ncol_base = nt * BN + wn * 64;
    const float* bm = g_bmix + b * OUT_F + ncol_base;
    float* Ob = out + (size_t)b * A_DIM * OUT_F;

#pragma unroll
    for (int mi = 0; mi < 4; mi++) {
        const int arow = mt * BM + wm * 64 + mi * 16 + (lane >> 2);
        float* r0 = Ob + (size_t)arow * OUT_F + ncol_base;
        float* r1 = r0 + 8 * OUT_F;
#pragma unroll
        for (int nj = 0; nj < 8; nj++) {
            const int nc = nj * 8 + 2 * (lane & 3);
            float2 bb = *reinterpret_cast<const float2*>(bm + nc);
            float2 v0 = make_float2(acc[mi][nj][0] + bb.x, acc[mi][nj][1] + bb.y);
            float2 v1 = make_float2(acc[mi][nj][2] + bb.x, acc[mi][nj][3] + bb.y);
            *reinterpret_cast<float2*>(r0 + nc) = v0;
            *reinterpret_cast<float2*>(r1 + nc) = v1;
        }
    }
}

// ============================================================
extern "C" void kernel_launch(void* const* d_in, const int* in_sizes, int n_in,
                              void* d_out, int out_size) {
    const float* x    = (const float*)d_in[0];   // [8,512,1024]
    const float* sp   = (const float*)d_in[1];   // [8,16]
    const float* W    = (const float*)d_in[2];   // [16,1024,1024]
    const float* bias = (const float*)d_in[3];   // [16,1024]
    float* out = (float*)d_out;                  // [8,512,1024]

    cudaFuncSetAttribute(gemm_mma_kernel,
                         cudaFuncAttributeMaxDynamicSharedMemorySize, SMEM_BYTES);

    prep_kernel<<<PREP_BLOCKS, 256>>>(W, x, bias, sp);

    dim3 grid(NTG, MT, BATCH);   // (4,4,8) = 128 CTAs, one wave
    gemm_mma_kernel<<<grid, 256, SMEM_BYTES>>>(out);
}

// round 9
// speedup vs baseline: 1.0648x; 1.0648x over previous
#include <cuda_runtime.h>
#include <cuda_bf16.h>
#include <cuda_fp16.h>
#include <cstdint>

#define N_OPT 16
#define OUT_F 1024
#define IN_F  1024
#define BATCH 8
#define A_DIM 512

// GEMM tiling
#define BM 128
#define BN 256
#define BKC 64                    // fp16 K elems per stage
#define NSTAGE 4
#define NKC (IN_F / BKC)          // 16
#define MT (A_DIM / BM)           // 4
#define NTG (OUT_F / BN)          // 4

#define A_BLK_BYTES (BM * 128)    // 16384
#define B_BLK_BYTES (BN * 128)    // 32768
#define STAGE_BYTES (A_BLK_BYTES + B_BLK_BYTES)   // 49152
#define SMEM_BYTES  (1024 + NSTAGE * STAGE_BYTES) // 197632

#define CONVX_BLOCKS 2048         // (BATCH*A_DIM*IN_F/8)/256
#define BIAS_BLOCKS 32

// ---- scratch (device globals; no allocation anywhere) ----
__device__ __align__(1024) __half g_xs[BATCH * A_DIM * IN_F];   // 8 MB staged fp16 x
__device__ __align__(1024) __half g_ws[BATCH * OUT_F * IN_F];   // 16 MB staged fp16 w_mixed
__device__ float g_bmix[BATCH * OUT_F];

// ================= PTX helpers (plain-sm_103-safe) =================
__device__ __forceinline__ uint32_t smem_u32(const void* p) {
    uint32_t a;
    asm("{ .reg .u64 t; cvta.to.shared.u64 t, %1; cvt.u32.u64 %0, t; }" : "=r"(a) : "l"(p));
    return a;
}
#define MBAR_INIT(addr, cnt) \
    asm volatile("mbarrier.init.shared.b64 [%0], %1;" :: "r"(addr), "r"(cnt) : "memory")
#define MBAR_EXPECT_TX(addr, bytes) \
    asm volatile("mbarrier.arrive.expect_tx.shared.b64 _, [%0], %1;" :: "r"(addr), "r"(bytes) : "memory")
#define MBAR_ARRIVE(addr) \
    asm volatile("mbarrier.arrive.shared.b64 _, [%0];" :: "r"(addr) : "memory")
__device__ __forceinline__ void mbar_wait(uint32_t mbar, uint32_t parity) {
    asm volatile(
        "{\n\t.reg .pred P;\n\t"
        "WL_%=:\n\t"
        "mbarrier.try_wait.parity.acquire.cta.shared::cta.b64 P, [%0], %1, 0x989680;\n\t"
        "@!P bra WL_%=;\n\t}"
        :: "r"(mbar), "r"(parity) : "memory");
}
#define BULK_G2S(dst, src, bytes, mbar) \
    asm volatile("cp.async.bulk.shared::cluster.global.mbarrier::complete_tx::bytes [%0], [%1], %2, [%3];" \
                 :: "r"(dst), "l"(src), "r"(bytes), "r"(mbar) : "memory")

__device__ __forceinline__ void ldsm_x4(uint32_t* r, uint32_t addr) {
    asm volatile("ldmatrix.sync.aligned.m8n8.x4.shared.b16 {%0,%1,%2,%3}, [%4];"
        : "=r"(r[0]), "=r"(r[1]), "=r"(r[2]), "=r"(r[3]) : "r"(addr));
}
__device__ __forceinline__ void mma_f16(float* d, const uint32_t* a, const uint32_t* b) {
    asm volatile(
        "mma.sync.aligned.m16n8k16.row.col.f32.f16.f16.f32 "
        "{%0,%1,%2,%3}, {%4,%5,%6,%7}, {%8,%9}, {%0,%1,%2,%3};"
        : "+f"(d[0]), "+f"(d[1]), "+f"(d[2]), "+f"(d[3])
        : "r"(a[0]), "r"(a[1]), "r"(a[2]), "r"(a[3]), "r"(b[0]), "r"(b[1]));
}

__device__ __forceinline__ uint32_t pk2h(float a, float b) {
    __half2 t = __floats2half2_rn(a, b);
    return *reinterpret_cast<uint32_t*>(&t);
}

// ============================================================
// Kernel 1: mix weights -> staged fp16 (R7-proven version).
// Staged layout: block(b, nt, kc) of 32 KB, kc = k-chunk of 64 elems.
// Row r is 128 B = 8 chunks of 16 B; chunk ch at byte ((ch ^ (r&7))*16).
// ============================================================
__global__ void mix_weights_kernel(const float* __restrict__ W,
                                   const float* __restrict__ sp) {
    __shared__ float s_sp[BATCH * N_OPT];
    if (threadIdx.x < BATCH * N_OPT) s_sp[threadIdx.x] = sp[threadIdx.x];
    __syncthreads();

    const int t = blockIdx.x * blockDim.x + threadIdx.x;
    const int i  = t >> 7;
    const int k0 = (t & 127) * 8;
    const int nt = i >> 8, r = i & 255;
    const int kc = k0 >> 6;
    const int ch = (k0 & 63) >> 3;

    const int plane4 = (OUT_F * IN_F) / 4;
    const float4* W4 = reinterpret_cast<const float4*>(W);

    float acc[BATCH][8];
#pragma unroll
    for (int b = 0; b < BATCH; b++)
#pragma unroll
        for (int q = 0; q < 8; q++) acc[b][q] = 0.f;

#pragma unroll
    for (int n = 0; n < N_OPT; n++) {
        float4 w0 = W4[(size_t)n * plane4 + t * 2];
        float4 w1 = W4[(size_t)n * plane4 + t * 2 + 1];
#pragma unroll
        for (int b = 0; b < BATCH; b++) {
            float s = s_sp[b * N_OPT + n];
            acc[b][0] += s * w0.x; acc[b][1] += s * w0.y;
            acc[b][2] += s * w0.z; acc[b][3] += s * w0.w;
            acc[b][4] += s * w1.x; acc[b][5] += s * w1.y;
            acc[b][6] += s * w1.z; acc[b][7] += s * w1.w;
        }
    }

    const uint32_t off = (uint32_t)r * 128 + (uint32_t)((ch ^ (r & 7)) * 16);
    char* base = (char*)g_ws;
#pragma unroll
    for (int b = 0; b < BATCH; b++) {
        uint4 hi = make_uint4(pk2h(acc[b][0], acc[b][1]), pk2h(acc[b][2], acc[b][3]),
                              pk2h(acc[b][4], acc[b][5]), pk2h(acc[b][6], acc[b][7]));
        size_t blk = ((size_t)(b * NTG + nt) * NKC + kc) * B_BLK_BYTES;
        *reinterpret_cast<uint4*>(base + blk + off) = hi;
    }
}

// ============================================================
// Kernel 2: convert x -> staged fp16, plus bias mix in tail blocks.
// ============================================================
__global__ void convert_x_bias_kernel(const float* __restrict__ x,
                                      const float* __restrict__ bias,
                                      const float* __restrict__ sp) {
    const int blk = blockIdx.x;
    if (blk < CONVX_BLOCKS) {
        const int t = blk * 256 + threadIdx.x;
        const int per_b8 = (A_DIM * IN_F) / 8;
        const int b = t / per_b8;
        const int rem = t % per_b8;
        const int a  = rem >> 7;
        const int k0 = (rem & 127) * 8;
        const int mt = a >> 7, r = a & 127;
        const int kc = k0 >> 6;
        const int ch = (k0 & 63) >> 3;

        const float4* x4 = reinterpret_cast<const float4*>(x);
        float4 v0 = x4[t * 2], v1 = x4[t * 2 + 1];

        uint4 hi = make_uint4(pk2h(v0.x, v0.y), pk2h(v0.z, v0.w),
                              pk2h(v1.x, v1.y), pk2h(v1.z, v1.w));

        const uint32_t off = (uint32_t)r * 128 + (uint32_t)((ch ^ (r & 7)) * 16);
        size_t blkoff = ((size_t)(b * MT + mt) * NKC + kc) * A_BLK_BYTES;
        *reinterpret_cast<uint4*>((char*)g_xs + blkoff + off) = hi;
    } else {
        int tid = (blk - CONVX_BLOCKS) * 256 + threadIdx.x;
        if (tid < BATCH * OUT_F) {
            int b = tid / OUT_F, i = tid % OUT_F;
            float acc = 0.f;
#pragma unroll
            for (int n = 0; n < N_OPT; n++) acc += sp[b * N_OPT + n] * bias[n * OUT_F + i];
            g_bmix[tid] = acc;
        }
    }
}

// ============================================================
// Kernel 3: fp16 HMMA GEMM, 512 threads / 16 warps (4 per SMSP).
// CTA tile 128x256, warp grid 2x8, warp tile 64x32.
// cp.async.bulk 4-stage pipe, 64 K per stage (4 k16 sub-steps,
// compiler-scheduled — no manual frag double-buffering).
// grid (4,4,8) = 128 CTAs, one wave.
// ============================================================
__global__ void __launch_bounds__(512, 1)
gemm_mma_kernel(float* __restrict__ out) {
    extern __shared__ char dsmem[];
    const uint32_t sbase = smem_u32(dsmem);
    const uint32_t data  = (sbase + 64 + 1023u) & ~1023u;
    uint32_t mb_full[NSTAGE], mb_empty[NSTAGE];
#pragma unroll
    for (int s = 0; s < NSTAGE; s++) { mb_full[s] = sbase + s * 8; mb_empty[s] = sbase + 32 + s * 8; }

    const int tid = threadIdx.x, lane = tid & 31, wid = tid >> 5;
    const int wm = wid >> 3, wn = wid & 7;           // 2 x 8 warp grid
    const int nt = blockIdx.x, mt = blockIdx.y, b = blockIdx.z;

    const char* Ag = (const char*)g_xs + (size_t)((b * MT + mt) * NKC) * A_BLK_BYTES;
    const char* Bg = (const char*)g_ws + (size_t)((b * NTG + nt) * NKC) * B_BLK_BYTES;

    if (tid == 0) {
#pragma unroll
        for (int s = 0; s < NSTAGE; s++) { MBAR_INIT(mb_full[s], 1); MBAR_INIT(mb_empty[s], 16); }
    }
    __syncthreads();

    if (tid == 0) {
#pragma unroll
        for (int p = 0; p < NSTAGE - 1; p++) {
            MBAR_EXPECT_TX(mb_full[p], STAGE_BYTES);
            BULK_G2S(data + p * STAGE_BYTES,               Ag + (size_t)p * A_BLK_BYTES, A_BLK_BYTES, mb_full[p]);
            BULK_G2S(data + p * STAGE_BYTES + A_BLK_BYTES, Bg + (size_t)p * B_BLK_BYTES, B_BLK_BYTES, mb_full[p]);
        }
    }

    const int a_row0 = wm * 64 + (lane & 15);        // M rows for A frags
    const int a_csel = lane >> 4;
    const int b_row0 = wn * 32 + (lane & 7) + ((lane >> 4) << 3);  // N rows for B frags
    const int b_csel = (lane >> 3) & 1;

    float acc[4][4][4];                              // mi x (ni*2+jj) x quad
#pragma unroll
    for (int mi = 0; mi < 4; mi++)
#pragma unroll
        for (int nj = 0; nj < 4; nj++)
#pragma unroll
            for (int q = 0; q < 4; q++) acc[mi][nj][q] = 0.f;

    for (int kc = 0; kc < NKC; kc++) {
        const int s = kc & (NSTAGE - 1);

        if (tid == 0 && kc + NSTAGE - 1 < NKC) {
            const int q = kc + NSTAGE - 1;
            const int ps = q & (NSTAGE - 1);
            if (kc >= 1) mbar_wait(mb_empty[ps], ((kc - 1) >> 2) & 1);
            MBAR_EXPECT_TX(mb_full[ps], STAGE_BYTES);
            BULK_G2S(data + ps * STAGE_BYTES,               Ag + (size_t)q * A_BLK_BYTES, A_BLK_BYTES, mb_full[ps]);
            BULK_G2S(data + ps * STAGE_BYTES + A_BLK_BYTES, Bg + (size_t)q * B_BLK_BYTES, B_BLK_BYTES, mb_full[ps]);
        }

        mbar_wait(mb_full[s], (kc >> 2) & 1);

        const uint32_t Abase = data + s * STAGE_BYTES;
        const uint32_t Bbase = Abase + A_BLK_BYTES;

#pragma unroll
        for (int u = 0; u < 4; u++) {                // four k16 sub-steps per stage
            uint32_t Ah[4][4], Bh[2][4];
#pragma unroll
            for (int mi = 0; mi < 4; mi++) {
                int row = a_row0 + mi * 16;
                int ch = (u * 2 + a_csel) ^ (row & 7);
                ldsm_x4(Ah[mi], Abase + row * 128 + ch * 16);
            }
#pragma unroll
            for (int ni = 0; ni < 2; ni++) {
                int row = b_row0 + ni * 16;
                int ch = (u * 2 + b_csel) ^ (row & 7);
                ldsm_x4(Bh[ni], Bbase + row * 128 + ch * 16);
            }
            if (u == 3 && lane == 0) MBAR_ARRIVE(mb_empty[s]);

#pragma unroll
            for (int mi = 0; mi < 4; mi++)
#pragma unroll
                for (int ni = 0; ni < 2; ni++)
#pragma unroll
                    for (int jj = 0; jj < 2; jj++)
                        mma_f16(acc[mi][ni * 2 + jj], Ah[mi], &Bh[ni][jj * 2]);
        }
    }

    // epilogue: add mixed bias, store
    const int ncol_base = nt * BN + wn * 32;
    const float* bm = g_bmix + b * OUT_F + ncol_base;
    float* Ob = out + (size_t)b * A_DIM * OUT_F;

#pragma unroll
    for (int mi = 0; mi < 4; mi++) {
        const int arow = mt * BM + wm * 64 + mi * 16 + (lane >> 2);
        float* r0 = Ob + (size_t)arow * OUT_F + ncol_base;
        float* r1 = r0 + 8 * OUT_F;
#pragma unroll
        for (int nj = 0; nj < 4; nj++) {
            const int nc = nj * 8 + 2 * (lane & 3);
            float2 bb = *reinterpret_cast<const float2*>(bm + nc);
            float2 v0 = make_float2(acc[mi][nj][0] + bb.x, acc[mi][nj][1] + bb.y);
            float2 v1 = make_float2(acc[mi][nj][2] + bb.x, acc[mi][nj][3] + bb.y);
            *reinterpret_cast<float2*>(r0 + nc) = v0;
            *reinterpret_cast<float2*>(r1 + nc) = v1;
        }
    }
}

// ============================================================
extern "C" void kernel_launch(void* const* d_in, const int* in_sizes, int n_in,
                              void* d_out, int out_size) {
    const float* x    = (const float*)d_in[0];   // [8,512,1024]
    const float* sp   = (const float*)d_in[1];   // [8,16]
    const float* W    = (const float*)d_in[2];   // [16,1024,1024]
    const float* bias = (const float*)d_in[3];   // [16,1024]
    float* out = (float*)d_out;                  // [8,512,1024]

    cudaFuncSetAttribute(gemm_mma_kernel,
                         cudaFuncAttributeMaxDynamicSharedMemorySize, SMEM_BYTES);

    mix_weights_kernel<<<(OUT_F * IN_F / 8) / 256, 256>>>(W, sp);
    convert_x_bias_kernel<<<CONVX_BLOCKS + BIAS_BLOCKS, 256>>>(x, bias, sp);

    dim3 grid(NTG, MT, BATCH);   // (4,4,8) = 128 CTAs, one wave
    gemm_mma_kernel<<<grid, 512, SMEM_BYTES>>>(out);
}

// round 10
// speedup vs baseline: 1.1541x; 1.0839x over previous
#include <cuda_runtime.h>
#include <cuda_bf16.h>
#include <cuda_fp16.h>
#include <cstdint>

#define N_OPT 16
#define OUT_F 1024
#define IN_F  1024
#define BATCH 8
#define A_DIM 512

// GEMM tiling
#define BM 128
#define BN 256
#define BKC 64                    // fp16 K elems per stage
#define NSTAGE 4
#define NKC (IN_F / BKC)          // 16
#define MT (A_DIM / BM)           // 4
#define NTG (OUT_F / BN)          // 4

#define A_BLK_BYTES (BM * 128)    // 16384
#define B_BLK_BYTES (BN * 128)    // 32768
#define STAGE_BYTES (A_BLK_BYTES + B_BLK_BYTES)   // 49152
#define SMEM_BYTES  (1024 + NSTAGE * STAGE_BYTES) // 197632

#define CONVX_BLOCKS 2048         // (BATCH*A_DIM*IN_F/8)/256
#define BIAS_BLOCKS 32

// ---- scratch (device globals; no allocation anywhere) ----
__device__ __align__(1024) __half g_xs[BATCH * A_DIM * IN_F];   // 8 MB staged fp16 x
__device__ __align__(1024) __half g_ws[BATCH * OUT_F * IN_F];   // 16 MB staged fp16 w_mixed
__device__ float g_bmix[BATCH * OUT_F];

// ================= PTX helpers (plain-sm_103-safe) =================
__device__ __forceinline__ uint32_t smem_u32(const void* p) {
    uint32_t a;
    asm("{ .reg .u64 t; cvta.to.shared.u64 t, %1; cvt.u32.u64 %0, t; }" : "=r"(a) : "l"(p));
    return a;
}
#define MBAR_INIT(addr, cnt) \
    asm volatile("mbarrier.init.shared.b64 [%0], %1;" :: "r"(addr), "r"(cnt) : "memory")
#define MBAR_EXPECT_TX(addr, bytes) \
    asm volatile("mbarrier.arrive.expect_tx.shared.b64 _, [%0], %1;" :: "r"(addr), "r"(bytes) : "memory")
#define MBAR_ARRIVE(addr) \
    asm volatile("mbarrier.arrive.shared.b64 _, [%0];" :: "r"(addr) : "memory")
__device__ __forceinline__ void mbar_wait(uint32_t mbar, uint32_t parity) {
    asm volatile(
        "{\n\t.reg .pred P;\n\t"
        "WL_%=:\n\t"
        "mbarrier.try_wait.parity.acquire.cta.shared::cta.b64 P, [%0], %1, 0x989680;\n\t"
        "@!P bra WL_%=;\n\t}"
        :: "r"(mbar), "r"(parity) : "memory");
}
#define BULK_G2S(dst, src, bytes, mbar) \
    asm volatile("cp.async.bulk.shared::cluster.global.mbarrier::complete_tx::bytes [%0], [%1], %2, [%3];" \
                 :: "r"(dst), "l"(src), "r"(bytes), "r"(mbar) : "memory")

__device__ __forceinline__ void ldsm_x4(uint32_t* r, uint32_t addr) {
    asm volatile("ldmatrix.sync.aligned.m8n8.x4.shared.b16 {%0,%1,%2,%3}, [%4];"
        : "=r"(r[0]), "=r"(r[1]), "=r"(r[2]), "=r"(r[3]) : "r"(addr));
}
__device__ __forceinline__ void mma_f16(float* d, const uint32_t* a, const uint32_t* b) {
    asm volatile(
        "mma.sync.aligned.m16n8k16.row.col.f32.f16.f16.f32 "
        "{%0,%1,%2,%3}, {%4,%5,%6,%7}, {%8,%9}, {%0,%1,%2,%3};"
        : "+f"(d[0]), "+f"(d[1]), "+f"(d[2]), "+f"(d[3])
        : "r"(a[0]), "r"(a[1]), "r"(a[2]), "r"(a[3]), "r"(b[0]), "r"(b[1]));
}

__device__ __forceinline__ uint32_t pk2h(float a, float b) {
    __half2 t = __floats2half2_rn(a, b);
    return *reinterpret_cast<uint32_t*>(&t);
}

// ============================================================
// Kernel 1: mix weights -> staged fp16. HIGH-OCCUPANCY version:
// each thread owns ONE float4 (4 k-elems) of one out-feature row,
// accumulates all 8 batches (acc[8][4] = 32 regs), W read exactly once.
// 1024 blocks x 256 threads; ~3-4 blocks/SM resident.
// Staged layout: block(b, nt, kc) of 32 KB, kc = k-chunk of 64 elems.
// Row r is 128 B = 8 chunks of 16 B; chunk ch at byte ((ch ^ (r&7))*16).
// ============================================================
__global__ void __launch_bounds__(256)
mix_weights_kernel(const float* __restrict__ W, const float* __restrict__ sp) {
    __shared__ float s_sp[BATCH * N_OPT];
    if (threadIdx.x < BATCH * N_OPT) s_sp[threadIdx.x] = sp[threadIdx.x];
    __syncthreads();

    const int t = blockIdx.x * blockDim.x + threadIdx.x;   // float4 index in plane
    const int i  = t >> 8;                 // out feature 0..1023
    const int k0 = (t & 255) * 4;          // k offset
    const int nt = i >> 8, r = i & 255;
    const int kc = k0 >> 6;
    const int ch = (k0 & 63) >> 3;
    const int sub = (k0 & 7) * 2;          // 0 or 8 bytes within 16B chunk

    const int plane4 = (OUT_F * IN_F) / 4;
    const float4* W4 = reinterpret_cast<const float4*>(W);

    float acc[BATCH][4];
#pragma unroll
    for (int b = 0; b < BATCH; b++)
#pragma unroll
        for (int q = 0; q < 4; q++) acc[b][q] = 0.f;

#pragma unroll
    for (int n = 0; n < N_OPT; n++) {
        float4 w = W4[(size_t)n * plane4 + t];
#pragma unroll
        for (int b = 0; b < BATCH; b++) {
            float s = s_sp[b * N_OPT + n];
            acc[b][0] += s * w.x; acc[b][1] += s * w.y;
            acc[b][2] += s * w.z; acc[b][3] += s * w.w;
        }
    }

    const uint32_t off = (uint32_t)r * 128 + (uint32_t)((ch ^ (r & 7)) * 16) + sub;
    char* base = (char*)g_ws;
#pragma unroll
    for (int b = 0; b < BATCH; b++) {
        uint2 hv = make_uint2(pk2h(acc[b][0], acc[b][1]), pk2h(acc[b][2], acc[b][3]));
        size_t blk = ((size_t)(b * NTG + nt) * NKC + kc) * B_BLK_BYTES;
        *reinterpret_cast<uint2*>(base + blk + off) = hv;
    }
}

// ============================================================
// Kernel 2: convert x -> staged fp16, plus bias mix in tail blocks.
// ============================================================
__global__ void convert_x_bias_kernel(const float* __restrict__ x,
                                      const float* __restrict__ bias,
                                      const float* __restrict__ sp) {
    const int blk = blockIdx.x;
    if (blk < CONVX_BLOCKS) {
        const int t = blk * 256 + threadIdx.x;
        const int per_b8 = (A_DIM * IN_F) / 8;
        const int b = t / per_b8;
        const int rem = t % per_b8;
        const int a  = rem >> 7;
        const int k0 = (rem & 127) * 8;
        const int mt = a >> 7, r = a & 127;
        const int kc = k0 >> 6;
        const int ch = (k0 & 63) >> 3;

        const float4* x4 = reinterpret_cast<const float4*>(x);
        float4 v0 = x4[t * 2], v1 = x4[t * 2 + 1];

        uint4 hi = make_uint4(pk2h(v0.x, v0.y), pk2h(v0.z, v0.w),
                              pk2h(v1.x, v1.y), pk2h(v1.z, v1.w));

        const uint32_t off = (uint32_t)r * 128 + (uint32_t)((ch ^ (r & 7)) * 16);
        size_t blkoff = ((size_t)(b * MT + mt) * NKC + kc) * A_BLK_BYTES;
        *reinterpret_cast<uint4*>((char*)g_xs + blkoff + off) = hi;
    } else {
        int tid = (blk - CONVX_BLOCKS) * 256 + threadIdx.x;
        if (tid < BATCH * OUT_F) {
            int b = tid / OUT_F, i = tid % OUT_F;
            float acc = 0.f;
#pragma unroll
            for (int n = 0; n < N_OPT; n++) acc += sp[b * N_OPT + n] * bias[n * OUT_F + i];
            g_bmix[tid] = acc;
        }
    }
}

// ============================================================
// Kernel 3: fp16 HMMA GEMM — exact R7-proven version (27.2 us).
// CTA 128x256, 8 warps (2x4), warp 64x64. cp.async.bulk 4-stage pipe,
// 64 K per stage (4 k16 sub-steps, compiler-scheduled).
// grid (4,4,8) = 128 CTAs, one wave.
// ============================================================
__global__ void __launch_bounds__(256, 1)
gemm_mma_kernel(float* __restrict__ out) {
    extern __shared__ char dsmem[];
    const uint32_t sbase = smem_u32(dsmem);
    const uint32_t data  = (sbase + 64 + 1023u) & ~1023u;
    uint32_t mb_full[NSTAGE], mb_empty[NSTAGE];
#pragma unroll
    for (int s = 0; s < NSTAGE; s++) { mb_full[s] = sbase + s * 8; mb_empty[s] = sbase + 32 + s * 8; }

    const int tid = threadIdx.x, lane = tid & 31, wid = tid >> 5;
    const int wm = wid >> 2, wn = wid & 3;
    const int nt = blockIdx.x, mt = blockIdx.y, b = blockIdx.z;

    const char* Ag = (const char*)g_xs + (size_t)((b * MT + mt) * NKC) * A_BLK_BYTES;
    const char* Bg = (const char*)g_ws + (size_t)((b * NTG + nt) * NKC) * B_BLK_BYTES;

    if (tid == 0) {
#pragma unroll
        for (int s = 0; s < NSTAGE; s++) { MBAR_INIT(mb_full[s], 1); MBAR_INIT(mb_empty[s], 8); }
    }
    __syncthreads();

    if (tid == 0) {
#pragma unroll
        for (int p = 0; p < NSTAGE - 1; p++) {
            MBAR_EXPECT_TX(mb_full[p], STAGE_BYTES);
            BULK_G2S(data + p * STAGE_BYTES,               Ag + (size_t)p * A_BLK_BYTES, A_BLK_BYTES, mb_full[p]);
            BULK_G2S(data + p * STAGE_BYTES + A_BLK_BYTES, Bg + (size_t)p * B_BLK_BYTES, B_BLK_BYTES, mb_full[p]);
        }
    }

    const int a_row0 = wm * 64 + (lane & 15);
    const int a_csel = lane >> 4;
    const int b_row0 = wn * 64 + (lane & 7) + ((lane >> 4) << 3);
    const int b_csel = (lane >> 3) & 1;

    float acc[4][8][4];
#pragma unroll
    for (int mi = 0; mi < 4; mi++)
#pragma unroll
        for (int nj = 0; nj < 8; nj++)
#pragma unroll
            for (int q = 0; q < 4; q++) acc[mi][nj][q] = 0.f;

    for (int kc = 0; kc < NKC; kc++) {
        const int s = kc & (NSTAGE - 1);

        if (tid == 0 && kc + NSTAGE - 1 < NKC) {
            const int q = kc + NSTAGE - 1;
            const int ps = q & (NSTAGE - 1);
            if (kc >= 1) mbar_wait(mb_empty[ps], ((kc - 1) >> 2) & 1);
            MBAR_EXPECT_TX(mb_full[ps], STAGE_BYTES);
            BULK_G2S(data + ps * STAGE_BYTES,               Ag + (size_t)q * A_BLK_BYTES, A_BLK_BYTES, mb_full[ps]);
            BULK_G2S(data + ps * STAGE_BYTES + A_BLK_BYTES, Bg + (size_t)q * B_BLK_BYTES, B_BLK_BYTES, mb_full[ps]);
        }

        mbar_wait(mb_full[s], (kc >> 2) & 1);

        const uint32_t Abase = data + s * STAGE_BYTES;
        const uint32_t Bbase = Abase + A_BLK_BYTES;

#pragma unroll
        for (int u = 0; u < 4; u++) {                     // four k16 sub-steps per stage
            uint32_t Ah[4][4], Bh[4][4];
#pragma unroll
            for (int mi = 0; mi < 4; mi++) {
                int row = a_row0 + mi * 16;
                int ch = (u * 2 + a_csel) ^ (row & 7);
                ldsm_x4(Ah[mi], Abase + row * 128 + ch * 16);
            }
#pragma unroll
            for (int ni = 0; ni < 4; ni++) {
                int row = b_row0 + ni * 16;
                int ch = (u * 2 + b_csel) ^ (row & 7);
                ldsm_x4(Bh[ni], Bbase + row * 128 + ch * 16);
            }
            if (u == 3 && lane == 0) MBAR_ARRIVE(mb_empty[s]);

#pragma unroll
            for (int mi = 0; mi < 4; mi++)
#pragma unroll
                for (int ni = 0; ni < 4; ni++)
#pragma unroll
                    for (int jj = 0; jj < 2; jj++)
                        mma_f16(acc[mi][ni * 2 + jj], Ah[mi], &Bh[ni][jj * 2]);
        }
    }

    // epilogue: add mixed bias, store
    const int ncol_base = nt * BN + wn * 64;
    const float* bm = g_bmix + b * OUT_F + ncol_base;
    float* Ob = out + (size_t)b * A_DIM * OUT_F;

#pragma unroll
    for (int mi = 0; mi < 4; mi++) {
        const int arow = mt * BM + wm * 64 + mi * 16 + (lane >> 2);
        float* r0 = Ob + (size_t)arow * OUT_F + ncol_base;
        float* r1 = r0 + 8 * OUT_F;
#pragma unroll
        for (int nj = 0; nj < 8; nj++) {
            const int nc = nj * 8 + 2 * (lane & 3);
            float2 bb = *reinterpret_cast<const float2*>(bm + nc);
            float2 v0 = make_float2(acc[mi][nj][0] + bb.x, acc[mi][nj][1] + bb.y);
            float2 v1 = make_float2(acc[mi][nj][2] + bb.x, acc[mi][nj][3] + bb.y);
            *reinterpret_cast<float2*>(r0 + nc) = v0;
            *reinterpret_cast<float2*>(r1 + nc) = v1;
        }
    }
}

// ============================================================
extern "C" void kernel_launch(void* const* d_in, const int* in_sizes, int n_in,
                              void* d_out, int out_size) {
    const float* x    = (const float*)d_in[0];   // [8,512,1024]
    const float* sp   = (const float*)d_in[1];   // [8,16]
    const float* W    = (const float*)d_in[2];   // [16,1024,1024]
    const float* bias = (const float*)d_in[3];   // [16,1024]
    float* out = (float*)d_out;                  // [8,512,1024]

    cudaFuncSetAttribute(gemm_mma_kernel,
                         cudaFuncAttributeMaxDynamicSharedMemorySize, SMEM_BYTES);

    mix_weights_kernel<<<(OUT_F * IN_F / 4) / 256, 256>>>(W, sp);   // 1024 blocks
    convert_x_bias_kernel<<<CONVX_BLOCKS + BIAS_BLOCKS, 256>>>(x, bias, sp);

    dim3 grid(NTG, MT, BATCH);   // (4,4,8) = 128 CTAs, one wave
    gemm_mma_kernel<<<grid, 256, SMEM_BYTES>>>(out);
}

// round 11
// speedup vs baseline: 1.2488x; 1.0820x over previous
#include <cuda_runtime.h>
#include <cuda_bf16.h>
#include <cuda_fp16.h>
#include <cstdint>

#define N_OPT 16
#define OUT_F 1024
#define IN_F  1024
#define BATCH 8
#define A_DIM 512

// GEMM tiling
#define BM 128
#define BN 256
#define BKC 64                    // fp16 K elems per stage
#define NSTAGE 4
#define NKC (IN_F / BKC)          // 16
#define MT (A_DIM / BM)           // 4
#define NTG (OUT_F / BN)          // 4

#define A_BLK_BYTES (BM * 128)    // 16384
#define B_BLK_BYTES (BN * 128)    // 32768
#define STAGE_BYTES (A_BLK_BYTES + B_BLK_BYTES)   // 49152
#define SMEM_BYTES  (1024 + NSTAGE * STAGE_BYTES) // 197632

#define CONVX_BLOCKS 2048         // (BATCH*A_DIM*IN_F/8)/256
#define BIAS_BLOCKS 32

// ---- scratch (device globals; no allocation anywhere) ----
__device__ __align__(1024) __half g_xs[BATCH * A_DIM * IN_F];   // 8 MB staged fp16 x
__device__ __align__(1024) __half g_ws[BATCH * OUT_F * IN_F];   // 16 MB staged fp16 w_mixed
__device__ float g_bmix[BATCH * OUT_F];

// ================= PTX helpers (plain-sm_103-safe) =================
__device__ __forceinline__ uint32_t smem_u32(const void* p) {
    uint32_t a;
    asm("{ .reg .u64 t; cvta.to.shared.u64 t, %1; cvt.u32.u64 %0, t; }" : "=r"(a) : "l"(p));
    return a;
}
#define MBAR_INIT(addr, cnt) \
    asm volatile("mbarrier.init.shared.b64 [%0], %1;" :: "r"(addr), "r"(cnt) : "memory")
#define MBAR_EXPECT_TX(addr, bytes) \
    asm volatile("mbarrier.arrive.expect_tx.shared.b64 _, [%0], %1;" :: "r"(addr), "r"(bytes) : "memory")
#define MBAR_ARRIVE(addr) \
    asm volatile("mbarrier.arrive.shared.b64 _, [%0];" :: "r"(addr) : "memory")
__device__ __forceinline__ void mbar_wait(uint32_t mbar, uint32_t parity) {
    asm volatile(
        "{\n\t.reg .pred P;\n\t"
        "WL_%=:\n\t"
        "mbarrier.try_wait.parity.acquire.cta.shared::cta.b64 P, [%0], %1, 0x989680;\n\t"
        "@!P bra WL_%=;\n\t}"
        :: "r"(mbar), "r"(parity) : "memory");
}
#define BULK_G2S(dst, src, bytes, mbar) \
    asm volatile("cp.async.bulk.shared::cluster.global.mbarrier::complete_tx::bytes [%0], [%1], %2, [%3];" \
                 :: "r"(dst), "l"(src), "r"(bytes), "r"(mbar) : "memory")

__device__ __forceinline__ void ldsm_x4(uint32_t* r, uint32_t addr) {
    asm volatile("ldmatrix.sync.aligned.m8n8.x4.shared.b16 {%0,%1,%2,%3}, [%4];"
        : "=r"(r[0]), "=r"(r[1]), "=r"(r[2]), "=r"(r[3]) : "r"(addr));
}
__device__ __forceinline__ void mma_f16(float* d, const uint32_t* a, const uint32_t* b) {
    asm volatile(
        "mma.sync.aligned.m16n8k16.row.col.f32.f16.f16.f32 "
        "{%0,%1,%2,%3}, {%4,%5,%6,%7}, {%8,%9}, {%0,%1,%2,%3};"
        : "+f"(d[0]), "+f"(d[1]), "+f"(d[2]), "+f"(d[3])
        : "r"(a[0]), "r"(a[1]), "r"(a[2]), "r"(a[3]), "r"(b[0]), "r"(b[1]));
}

__device__ __forceinline__ uint32_t pk2h(float a, float b) {
    __half2 t = __floats2half2_rn(a, b);
    return *reinterpret_cast<uint32_t*>(&t);
}

// ============================================================
// Kernel 1: mix weights -> staged fp16. MLP-batched version:
// two phases of 8 experts; each phase front-batches 8 independent
// float4 loads (MLP=8) before the FMA block. acc[8][4] = 32 regs,
// load buffer 32 regs; __launch_bounds__(256,3) pins 3 blocks/SM.
// Staged layout: block(b, nt, kc) of 32 KB, kc = k-chunk of 64 elems.
// Row r is 128 B = 8 chunks of 16 B; chunk ch at byte ((ch ^ (r&7))*16).
// ============================================================
__global__ void __launch_bounds__(256, 3)
mix_weights_kernel(const float* __restrict__ W, const float* __restrict__ sp) {
    __shared__ float s_sp[BATCH * N_OPT];
    if (threadIdx.x < BATCH * N_OPT) s_sp[threadIdx.x] = sp[threadIdx.x];
    __syncthreads();

    const int t = blockIdx.x * blockDim.x + threadIdx.x;   // float4 index in plane
    const int i  = t >> 8;                 // out feature 0..1023
    const int k0 = (t & 255) * 4;          // k offset
    const int nt = i >> 8, r = i & 255;
    const int kc = k0 >> 6;
    const int ch = (k0 & 63) >> 3;
    const int sub = (k0 & 7) * 2;          // 0 or 8 bytes within 16B chunk

    const int plane4 = (OUT_F * IN_F) / 4;
    const float4* W4 = reinterpret_cast<const float4*>(W);

    float acc[BATCH][4];
#pragma unroll
    for (int b = 0; b < BATCH; b++)
#pragma unroll
        for (int q = 0; q < 4; q++) acc[b][q] = 0.f;

#pragma unroll
    for (int g = 0; g < 2; g++) {
        // front-batch 8 independent loads (MLP = 8)
        float4 wv[8];
#pragma unroll
        for (int n = 0; n < 8; n++)
            wv[n] = W4[(size_t)(g * 8 + n) * plane4 + t];
        // accumulate
#pragma unroll
        for (int n = 0; n < 8; n++) {
#pragma unroll
            for (int b = 0; b < BATCH; b++) {
                float s = s_sp[b * N_OPT + g * 8 + n];
                acc[b][0] += s * wv[n].x; acc[b][1] += s * wv[n].y;
                acc[b][2] += s * wv[n].z; acc[b][3] += s * wv[n].w;
            }
        }
    }

    const uint32_t off = (uint32_t)r * 128 + (uint32_t)((ch ^ (r & 7)) * 16) + sub;
    char* base = (char*)g_ws;
#pragma unroll
    for (int b = 0; b < BATCH; b++) {
        uint2 hv = make_uint2(pk2h(acc[b][0], acc[b][1]), pk2h(acc[b][2], acc[b][3]));
        size_t blk = ((size_t)(b * NTG + nt) * NKC + kc) * B_BLK_BYTES;
        *reinterpret_cast<uint2*>(base + blk + off) = hv;
    }
}

// ============================================================
// Kernel 2: convert x -> staged fp16, plus bias mix in tail blocks.
// ============================================================
__global__ void convert_x_bias_kernel(const float* __restrict__ x,
                                      const float* __restrict__ bias,
                                      const float* __restrict__ sp) {
    const int blk = blockIdx.x;
    if (blk < CONVX_BLOCKS) {
        const int t = blk * 256 + threadIdx.x;
        const int per_b8 = (A_DIM * IN_F) / 8;
        const int b = t / per_b8;
        const int rem = t % per_b8;
        const int a  = rem >> 7;
        const int k0 = (rem & 127) * 8;
        const int mt = a >> 7, r = a & 127;
        const int kc = k0 >> 6;
        const int ch = (k0 & 63) >> 3;

        const float4* x4 = reinterpret_cast<const float4*>(x);
        float4 v0 = x4[t * 2], v1 = x4[t * 2 + 1];

        uint4 hi = make_uint4(pk2h(v0.x, v0.y), pk2h(v0.z, v0.w),
                              pk2h(v1.x, v1.y), pk2h(v1.z, v1.w));

        const uint32_t off = (uint32_t)r * 128 + (uint32_t)((ch ^ (r & 7)) * 16);
        size_t blkoff = ((size_t)(b * MT + mt) * NKC + kc) * A_BLK_BYTES;
        *reinterpret_cast<uint4*>((char*)g_xs + blkoff + off) = hi;
    } else {
        int tid = (blk - CONVX_BLOCKS) * 256 + threadIdx.x;
        if (tid < BATCH * OUT_F) {
            int b = tid / OUT_F, i = tid % OUT_F;
            float acc = 0.f;
#pragma unroll
            for (int n = 0; n < N_OPT; n++) acc += sp[b * N_OPT + n] * bias[n * OUT_F + i];
            g_bmix[tid] = acc;
        }
    }
}

// ============================================================
// Kernel 3: fp16 HMMA GEMM — exact R7-proven version (27.2 us).
// CTA 128x256, 8 warps (2x4), warp 64x64. cp.async.bulk 4-stage pipe,
// 64 K per stage (4 k16 sub-steps, compiler-scheduled).
// grid (4,4,8) = 128 CTAs, one wave.
// ============================================================
__global__ void __launch_bounds__(256, 1)
gemm_mma_kernel(float* __restrict__ out) {
    extern __shared__ char dsmem[];
    const uint32_t sbase = smem_u32(dsmem);
    const uint32_t data  = (sbase + 64 + 1023u) & ~1023u;
    uint32_t mb_full[NSTAGE], mb_empty[NSTAGE];
#pragma unroll
    for (int s = 0; s < NSTAGE; s++) { mb_full[s] = sbase + s * 8; mb_empty[s] = sbase + 32 + s * 8; }

    const int tid = threadIdx.x, lane = tid & 31, wid = tid >> 5;
    const int wm = wid >> 2, wn = wid & 3;
    const int nt = blockIdx.x, mt = blockIdx.y, b = blockIdx.z;

    const char* Ag = (const char*)g_xs + (size_t)((b * MT + mt) * NKC) * A_BLK_BYTES;
    const char* Bg = (const char*)g_ws + (size_t)((b * NTG + nt) * NKC) * B_BLK_BYTES;

    if (tid == 0) {
#pragma unroll
        for (int s = 0; s < NSTAGE; s++) { MBAR_INIT(mb_full[s], 1); MBAR_INIT(mb_empty[s], 8); }
    }
    __syncthreads();

    if (tid == 0) {
#pragma unroll
        for (int p = 0; p < NSTAGE - 1; p++) {
            MBAR_EXPECT_TX(mb_full[p], STAGE_BYTES);
            BULK_G2S(data + p * STAGE_BYTES,               Ag + (size_t)p * A_BLK_BYTES, A_BLK_BYTES, mb_full[p]);
            BULK_G2S(data + p * STAGE_BYTES + A_BLK_BYTES, Bg + (size_t)p * B_BLK_BYTES, B_BLK_BYTES, mb_full[p]);
        }
    }

    const int a_row0 = wm * 64 + (lane & 15);
    const int a_csel = lane >> 4;
    const int b_row0 = wn * 64 + (lane & 7) + ((lane >> 4) << 3);
    const int b_csel = (lane >> 3) & 1;

    float acc[4][8][4];
#pragma unroll
    for (int mi = 0; mi < 4; mi++)
#pragma unroll
        for (int nj = 0; nj < 8; nj++)
#pragma unroll
            for (int q = 0; q < 4; q++) acc[mi][nj][q] = 0.f;

    for (int kc = 0; kc < NKC; kc++) {
        const int s = kc & (NSTAGE - 1);

        if (tid == 0 && kc + NSTAGE - 1 < NKC) {
            const int q = kc + NSTAGE - 1;
            const int ps = q & (NSTAGE - 1);
            if (kc >= 1) mbar_wait(mb_empty[ps], ((kc - 1) >> 2) & 1);
            MBAR_EXPECT_TX(mb_full[ps], STAGE_BYTES);
            BULK_G2S(data + ps * STAGE_BYTES,               Ag + (size_t)q * A_BLK_BYTES, A_BLK_BYTES, mb_full[ps]);
            BULK_G2S(data + ps * STAGE_BYTES + A_BLK_BYTES, Bg + (size_t)q * B_BLK_BYTES, B_BLK_BYTES, mb_full[ps]);
        }

        mbar_wait(mb_full[s], (kc >> 2) & 1);

        const uint32_t Abase = data + s * STAGE_BYTES;
        const uint32_t Bbase = Abase + A_BLK_BYTES;

#pragma unroll
        for (int u = 0; u < 4; u++) {                     // four k16 sub-steps per stage
            uint32_t Ah[4][4], Bh[4][4];
#pragma unroll
            for (int mi = 0; mi < 4; mi++) {
                int row = a_row0 + mi * 16;
                int ch = (u * 2 + a_csel) ^ (row & 7);
                ldsm_x4(Ah[mi], Abase + row * 128 + ch * 16);
            }
#pragma unroll
            for (int ni = 0; ni < 4; ni++) {
                int row = b_row0 + ni * 16;
                int ch = (u * 2 + b_csel) ^ (row & 7);
                ldsm_x4(Bh[ni], Bbase + row * 128 + ch * 16);
            }
            if (u == 3 && lane == 0) MBAR_ARRIVE(mb_empty[s]);

#pragma unroll
            for (int mi = 0; mi < 4; mi++)
#pragma unroll
                for (int ni = 0; ni < 4; ni++)
#pragma unroll
                    for (int jj = 0; jj < 2; jj++)
                        mma_f16(acc[mi][ni * 2 + jj], Ah[mi], &Bh[ni][jj * 2]);
        }
    }

    // epilogue: add mixed bias, store
    const int ncol_base = nt * BN + wn * 64;
    const float* bm = g_bmix + b * OUT_F + ncol_base;
    float* Ob = out + (size_t)b * A_DIM * OUT_F;

#pragma unroll
    for (int mi = 0; mi < 4; mi++) {
        const int arow = mt * BM + wm * 64 + mi * 16 + (lane >> 2);
        float* r0 = Ob + (size_t)arow * OUT_F + ncol_base;
        float* r1 = r0 + 8 * OUT_F;
#pragma unroll
        for (int nj = 0; nj < 8; nj++) {
            const int nc = nj * 8 + 2 * (lane & 3);
            float2 bb = *reinterpret_cast<const float2*>(bm + nc);
            float2 v0 = make_float2(acc[mi][nj][0] + bb.x, acc[mi][nj][1] + bb.y);
            float2 v1 = make_float2(acc[mi][nj][2] + bb.x, acc[mi][nj][3] + bb.y);
            *reinterpret_cast<float2*>(r0 + nc) = v0;
            *reinterpret_cast<float2*>(r1 + nc) = v1;
        }
    }
}

// ============================================================
extern "C" void kernel_launch(void* const* d_in, const int* in_sizes, int n_in,
                              void* d_out, int out_size) {
    const float* x    = (const float*)d_in[0];   // [8,512,1024]
    const float* sp   = (const float*)d_in[1];   // [8,16]
    const float* W    = (const float*)d_in[2];   // [16,1024,1024]
    const float* bias = (const float*)d_in[3];   // [16,1024]
    float* out = (float*)d_out;                  // [8,512,1024]

    cudaFuncSetAttribute(gemm_mma_kernel,
                         cudaFuncAttributeMaxDynamicSharedMemorySize, SMEM_BYTES);

    mix_weights_kernel<<<(OUT_F * IN_F / 4) / 256, 256>>>(W, sp);   // 1024 blocks
    convert_x_bias_kernel<<<CONVX_BLOCKS + BIAS_BLOCKS, 256>>>(x, bias, sp);

    dim3 grid(NTG, MT, BATCH);   // (4,4,8) = 128 CTAs, one wave
    gemm_mma_kernel<<<grid, 256, SMEM_BYTES>>>(out);
}